// round 15
// baseline (speedup 1.0000x reference)
#include <cuda_runtime.h>
#include <cstdint>
#include <cstddef>

#define TT 2048
#define BB 32
#define HH 256
#define NCELL (TT * 2)
#define NCTA 128          // 32 clusters x 4 CTAs, one batch per cluster
#define NANPAT 0x7FC0DEADu

// ---------------- global scratch (allocation-free) ------------------------------
__device__ float g_gi[(size_t)TT * BB * 3 * HH];   // x @ w_ih^T + b_ih  [T][B][768]

// ---------------- helpers ---------------------------------------------------------
__device__ __forceinline__ uint32_t smem_u32(const void* p) {
  uint32_t a;
  asm("{ .reg .u64 t; cvta.to.shared.u64 t, %1; cvt.u32.u64 %0, t; }"
      : "=r"(a) : "l"(p));
  return a;
}
__device__ __forceinline__ uint64_t pack2(float a, float b) {
  uint64_t r;
  asm("mov.b64 %0, {%1, %2};" : "=l"(r) : "f"(a), "f"(b));
  return r;
}
__device__ __forceinline__ void unpack2(float& a, float& b, uint64_t v) {
  asm("mov.b64 {%0, %1}, %2;" : "=f"(a), "=f"(b) : "l"(v));
}
__device__ __forceinline__ void fma2(uint64_t& d, uint64_t a, uint64_t b) {
  asm("fma.rn.f32x2 %0, %1, %2, %0;" : "+l"(d) : "l"(a), "l"(b));
}
__device__ __forceinline__ float hadd(uint64_t v) {
  float a, b;
  unpack2(a, b, v);
  return a + b;
}
// gates: EXACT R12 formulation (true division) — measured rel_err 2.8e-5
__device__ __forceinline__ float sig_p(float x) {
  return 1.f / (1.f + __expf(-x));
}
__device__ __forceinline__ float tanh_p(float x) {
  return 2.f / (1.f + __expf(-2.f * x)) - 1.f;
}
// 4-byte store into CTA `rank`'s SMEM at this CTA's local offset
__device__ __forceinline__ void st_cluster_u32(uint32_t local_addr, uint32_t rank,
                                               uint32_t v) {
  asm volatile(
      "{\n\t.reg .b32 ra;\n\t"
      "mapa.shared::cluster.u32 ra, %0, %1;\n\t"
      "st.relaxed.cluster.shared::cluster.u32 [ra], %2;\n\t}"
      :: "r"(local_addr), "r"(rank), "r"(v) : "memory");
}
__device__ __forceinline__ uint32_t ld_vol_u32(uint32_t addr) {
  uint32_t v;
  asm volatile("ld.volatile.shared.u32 %0, [%1];" : "=r"(v) : "r"(addr) : "memory");
  return v;
}
__device__ __forceinline__ void st_smem_u32(uint32_t addr, uint32_t v) {
  asm volatile("st.shared.u32 [%0], %1;" :: "r"(addr), "r"(v) : "memory");
}
#define CLUSTER_SYNC_()                                              \
  do {                                                               \
    asm volatile("barrier.cluster.arrive.aligned;" ::: "memory");    \
    asm volatile("barrier.cluster.wait.aligned;" ::: "memory");      \
  } while (0)

// ---------------- gi precompute (f32x2 packed over k-pairs) -----------------------
__global__ __launch_bounds__(256) void gi_kernel(
    const float* __restrict__ x, const float* __restrict__ w_ih,
    const float* __restrict__ b_ih) {
  __shared__ float xs[32 * 260];
  __shared__ float ws[128 * 18];
  const int t   = blockIdx.x;
  const int gc0 = blockIdx.y * 128;
  const int tid = threadIdx.x;

  for (int i = tid; i < 2048; i += 256) {
    int b = i >> 6;
    int c4 = (i & 63) << 2;
    float4 v = *(const float4*)(x + ((size_t)b * TT + t) * HH + c4);
    *(float4*)(xs + b * 260 + c4) = v;
  }

  const int bq = tid >> 5;
  const int gq = tid & 31;

  uint64_t acc2[4][4];
#pragma unroll
  for (int i = 0; i < 4; i++)
#pragma unroll
    for (int j = 0; j < 4; j++) acc2[i][j] = pack2(0.f, 0.f);

  for (int kt = 0; kt < 16; ++kt) {
    const int k0 = kt * 16;
    __syncthreads();
    for (int i = tid; i < 1024; i += 256) {
      int r = i >> 3;
      int c2 = (i & 7) << 1;
      *(float2*)(ws + r * 18 + c2) =
          *(const float2*)(w_ih + (size_t)(gc0 + r) * HH + k0 + c2);
    }
    __syncthreads();
#pragma unroll
    for (int kp = 0; kp < 8; ++kp) {
      const int kk = kp << 1;
      uint64_t w2[4];
#pragma unroll
      for (int j = 0; j < 4; j++)
        w2[j] = *(const uint64_t*)(ws + (gq + 32 * j) * 18 + kk);
#pragma unroll
      for (int i = 0; i < 4; i++) {
        const uint64_t x2 = *(const uint64_t*)(xs + (bq * 4 + i) * 260 + k0 + kk);
#pragma unroll
        for (int j = 0; j < 4; j++) fma2(acc2[i][j], x2, w2[j]);
      }
    }
  }
#pragma unroll
  for (int j = 0; j < 4; j++) {
    int g = gc0 + gq + 32 * j;
    float bias = b_ih[g];
#pragma unroll
    for (int i = 0; i < 4; i++) {
      float a, b;
      unpack2(a, b, acc2[i][j]);
      g_gi[((size_t)t * BB + (bq * 4 + i)) * 768 + g] = a + b + bias;
    }
  }
}

// ---------------- clustered recurrent scan: 4 CTAs / 1 batch ----------------------
// NaN-sentinel 4B protocol: bufs pre-filled with NANPAT; a publish is one 4B
// store (st.cluster remote / STS local); the slot's single poller reads it,
// stages to hT, and resets to NANPAT. No seq, no fences, no mbarriers.
__global__ __launch_bounds__(256, 1) __cluster_dims__(4, 1, 1)
void scan_kernel(const float* __restrict__ hidden, const float* __restrict__ w_hh,
                 const float* __restrict__ b_hh, float* __restrict__ out) {
  __shared__ __align__(16) unsigned bufs[2][4 * 66];   // [parity][padded slot]
  __shared__ __align__(16) float hT[4 * 66];           // padded 64-col slices

  const int tid  = threadIdx.x;
  const int rank = blockIdx.x & 3;
  const int b    = blockIdx.x >> 2;    // batch (0..31)
  const int warp = tid >> 5;
  const int lane = tid & 31;
  const int kq   = lane & 3;           // K-slice [kq*64, kq*64+64) floats
  const int colL = warp * 8 + (lane >> 2);   // 0..63
  const int col  = rank * 64 + colL;   // global column (this CTA's output col)

  // ---- persistent weights: 3 gates x 32 k-pairs = 96 u64 regs ----
  uint64_t w2[3][32];
#pragma unroll
  for (int g = 0; g < 3; ++g) {
    const uint64_t* wp =
        (const uint64_t*)(w_hh + (size_t)(g * HH + col) * HH + kq * 64);
#pragma unroll
    for (int kp = 0; kp < 32; ++kp) w2[g][kp] = wp[kp];
  }
  const float br = b_hh[0 * HH + col];
  const float bz = b_hh[1 * HH + col];
  const float bn = b_hh[2 * HH + col];

  // ---- init: sentinel-fill bufs; initial h into hT ----
  for (int i = tid; i < 2 * 4 * 66; i += 256) ((unsigned*)bufs)[i] = NANPAT;
  for (int i = tid; i < HH; i += 256)
    hT[(i >> 6) * 66 + (i & 63)] = hidden[(size_t)b * HH + i];
  float hold = hidden[(size_t)b * HH + col];   // register-carried h for own col
  __syncthreads();
  CLUSTER_SYNC_();   // sentinel bufs visible before any peer publishes

  const int slot = (tid >> 6) * 66 + (tid & 63);       // this thread's poll slot
  const uint32_t pollA = smem_u32(&bufs[0][0]) + (uint32_t)slot * 4u;
  const uint32_t pollB = pollA + 4u * 66u * 4u;
  const int colSlot = (col >> 6) * 66 + (col & 63);    // publish slot for col
  const uint32_t dstA = smem_u32(&bufs[0][0]) + (uint32_t)colSlot * 4u;
  const uint32_t dstB = dstA + 4u * 66u * 4u;
  const int hTpos = slot;

  // gi registers for current t (shared by both layer cells of t)
  const float* gp0 = g_gi + (size_t)b * 768 + col;
  float gir = __ldg(gp0);
  float giz = __ldg(gp0 + 256);
  float gin = __ldg(gp0 + 512);

  for (int cell = 0; cell < NCELL; ++cell) {
    // ---- poll own slot (4B, tight spin), stage to hT, reset sentinel ----
    if (cell > 0) {
      const uint32_t pa = (cell & 1) ? pollB : pollA;
      uint32_t v = ld_vol_u32(pa);
      int spins = 0;
      while (v == NANPAT) {
        if (++spins > 128) __nanosleep(20);
        v = ld_vol_u32(pa);
      }
      hT[hTpos] = __uint_as_float(v);
      st_smem_u32(pa, NANPAT);   // single-poller reset; next writer is tag+2
      __syncthreads();
    }

    // ---- FMA: 96 fma2 (3 gates x 32 k-pairs), conflict-free broadcast LDS ----
    uint64_t aR = pack2(0.f, 0.f), aZ = aR, aN = aR;
    const uint64_t* H = (const uint64_t*)(&hT[kq * 66]);
#pragma unroll
    for (int kp = 0; kp < 32; ++kp) {
      const uint64_t h2 = H[kp];
      fma2(aR, w2[0][kp], h2);
      fma2(aZ, w2[1][kp], h2);
      fma2(aN, w2[2][kp], h2);
    }
    float sR = hadd(aR), sZ = hadd(aZ), sN = hadd(aN);
    // butterfly over kq (lane bits 0..1): 2 rounds x 3 values
#pragma unroll
    for (int m = 1; m <= 2; m <<= 1) {
      sR += __shfl_xor_sync(0xffffffffu, sR, m);
      sZ += __shfl_xor_sync(0xffffffffu, sZ, m);
      sN += __shfl_xor_sync(0xffffffffu, sN, m);
    }

    // ---- gates (exact R12 formulation), redundant across kq lanes ----
    const float r = sig_p(gir + sR + br);
    const float z = sig_p(giz + sZ + bz);
    const float n = tanh_p(gin + r * (sN + bn));
    const float hn = (1.f - z) * n + z * hold;
    hold = hn;                                  // register-carried for next cell

    // ---- publish (critical path): each thread ONE 4B store to rank kq ----
    if (cell + 1 < NCELL) {
      const uint32_t bits = __float_as_uint(hn);
      const uint32_t dst = ((cell + 1) & 1) ? dstB : dstA;
      if (kq == rank)
        st_smem_u32(dst, bits);                 // local delivery: plain STS
      else
        st_cluster_u32(dst, (uint32_t)kq, bits);
    }
    // ---- off critical path: output store + gi prefetch for next t ----
    if (cell & 1) {
      if (kq == 3)
        out[((size_t)(cell >> 1) * BB + b) * HH + col] = hn;
      if (cell + 1 < NCELL) {   // next cell starts a new t: reload gi (hidden)
        const float* gp =
            g_gi + ((size_t)((cell + 1) >> 1) * BB + b) * 768 + col;
        gir = __ldg(gp);
        giz = __ldg(gp + 256);
        gin = __ldg(gp + 512);
      }
    }
  }
  CLUSTER_SYNC_();   // no CTA exits while peers may still store into its SMEM
}

// ---------------- launch ----------------------------------------------------------
extern "C" void kernel_launch(void* const* d_in, const int* in_sizes, int n_in,
                              void* d_out, int out_size) {
  const float *input = 0, *hidden = 0, *w_ih = 0, *w_hh = 0, *b_ih = 0, *b_hh = 0;
  for (int i = 0; i < n_in; ++i) {
    long s = in_sizes[i];
    if (s == (long)BB * TT * HH) {
      input = (const float*)d_in[i];
    } else if (s == BB * HH && !hidden) {
      hidden = (const float*)d_in[i];
    } else if (s == 3 * HH * HH) {
      if (!w_ih) w_ih = (const float*)d_in[i]; else w_hh = (const float*)d_in[i];
    } else if (s == 3 * HH) {
      if (!b_ih) b_ih = (const float*)d_in[i]; else b_hh = (const float*)d_in[i];
    }
  }
  gi_kernel<<<dim3(TT, 6), 256>>>(input, w_ih, b_ih);
  scan_kernel<<<NCTA, 256>>>(hidden, w_hh, b_hh, (float*)d_out);
}

// round 16
// speedup vs baseline: 1.1095x; 1.1095x over previous
#include <cuda_runtime.h>
#include <cstdint>
#include <cstddef>

#define TT 2048
#define BB 32
#define HH 256
#define NCELL (TT * 2)
#define NCTA 128          // 32 clusters x 4 CTAs, one batch per cluster

// ---------------- global scratch (allocation-free) ------------------------------
__device__ float g_gi[(size_t)TT * BB * 3 * HH];   // x @ w_ih^T + b_ih  [T][B][768]

// ---------------- helpers ---------------------------------------------------------
__device__ __forceinline__ uint32_t smem_u32(const void* p) {
  uint32_t a;
  asm("{ .reg .u64 t; cvta.to.shared.u64 t, %1; cvt.u32.u64 %0, t; }"
      : "=r"(a) : "l"(p));
  return a;
}
__device__ __forceinline__ uint64_t pack2(float a, float b) {
  uint64_t r;
  asm("mov.b64 %0, {%1, %2};" : "=l"(r) : "f"(a), "f"(b));
  return r;
}
__device__ __forceinline__ void unpack2(float& a, float& b, uint64_t v) {
  asm("mov.b64 {%0, %1}, %2;" : "=f"(a), "=f"(b) : "l"(v));
}
__device__ __forceinline__ void fma2(uint64_t& d, uint64_t a, uint64_t b) {
  asm("fma.rn.f32x2 %0, %1, %2, %0;" : "+l"(d) : "l"(a), "l"(b));
}
__device__ __forceinline__ float hadd(uint64_t v) {
  float a, b;
  unpack2(a, b, v);
  return a + b;
}
// reciprocal: rcp.approx + FMA-form Newton step -> ~0.5-1 ulp (accurate class)
__device__ __forceinline__ float rcp_fma(float d) {
  float r;
  asm("rcp.approx.f32 %0, %1;" : "=f"(r) : "f"(d));
  const float e = __fmaf_rn(-d, r, 1.f);
  return __fmaf_rn(r, e, r);
}
__device__ __forceinline__ float sig_f(float x) {
  return rcp_fma(1.f + __expf(-x));
}
__device__ __forceinline__ float tanh_f(float x) {
  return __fmaf_rn(2.f, rcp_fma(1.f + __expf(-2.f * x)), -1.f);
}
// store (value,seq) u64 into CTA `rank`'s SMEM at this CTA's local offset
__device__ __forceinline__ void st_cluster_u64(uint32_t local_addr, uint32_t rank,
                                               uint64_t v) {
  asm volatile(
      "{\n\t.reg .b32 ra;\n\t"
      "mapa.shared::cluster.u32 ra, %0, %1;\n\t"
      "st.relaxed.cluster.shared::cluster.u64 [ra], %2;\n\t}"
      :: "r"(local_addr), "r"(rank), "l"(v) : "memory");
}
__device__ __forceinline__ uint64_t ld_vol_u64(uint32_t addr) {
  uint64_t v;
  asm volatile("ld.volatile.shared.u64 %0, [%1];" : "=l"(v) : "r"(addr) : "memory");
  return v;
}
#define CLUSTER_SYNC_()                                              \
  do {                                                               \
    asm volatile("barrier.cluster.arrive.aligned;" ::: "memory");    \
    asm volatile("barrier.cluster.wait.aligned;" ::: "memory");      \
  } while (0)

// ---------------- gi precompute (f32x2 packed over k-pairs) -----------------------
__global__ __launch_bounds__(256) void gi_kernel(
    const float* __restrict__ x, const float* __restrict__ w_ih,
    const float* __restrict__ b_ih) {
  __shared__ float xs[32 * 260];
  __shared__ float ws[128 * 18];
  const int t   = blockIdx.x;
  const int gc0 = blockIdx.y * 128;
  const int tid = threadIdx.x;

  for (int i = tid; i < 2048; i += 256) {
    int b = i >> 6;
    int c4 = (i & 63) << 2;
    float4 v = *(const float4*)(x + ((size_t)b * TT + t) * HH + c4);
    *(float4*)(xs + b * 260 + c4) = v;
  }

  const int bq = tid >> 5;
  const int gq = tid & 31;

  uint64_t acc2[4][4];
#pragma unroll
  for (int i = 0; i < 4; i++)
#pragma unroll
    for (int j = 0; j < 4; j++) acc2[i][j] = pack2(0.f, 0.f);

  for (int kt = 0; kt < 16; ++kt) {
    const int k0 = kt * 16;
    __syncthreads();
    for (int i = tid; i < 1024; i += 256) {
      int r = i >> 3;
      int c2 = (i & 7) << 1;
      *(float2*)(ws + r * 18 + c2) =
          *(const float2*)(w_ih + (size_t)(gc0 + r) * HH + k0 + c2);
    }
    __syncthreads();
#pragma unroll
    for (int kp = 0; kp < 8; ++kp) {
      const int kk = kp << 1;
      uint64_t w2[4];
#pragma unroll
      for (int j = 0; j < 4; j++)
        w2[j] = *(const uint64_t*)(ws + (gq + 32 * j) * 18 + kk);
#pragma unroll
      for (int i = 0; i < 4; i++) {
        const uint64_t x2 = *(const uint64_t*)(xs + (bq * 4 + i) * 260 + k0 + kk);
#pragma unroll
        for (int j = 0; j < 4; j++) fma2(acc2[i][j], x2, w2[j]);
      }
    }
  }
#pragma unroll
  for (int j = 0; j < 4; j++) {
    int g = gc0 + gq + 32 * j;
    float bias = b_ih[g];
#pragma unroll
    for (int i = 0; i < 4; i++) {
      float a, b;
      unpack2(a, b, acc2[i][j]);
      g_gi[((size_t)t * BB + (bq * 4 + i)) * 768 + g] = a + b + bias;
    }
  }
}

// ---------------- clustered recurrent scan: 4 CTAs / 1 batch ----------------------
// Thread = (col, kq): 64 cols x 4 K-slices. Weights in 96 u64 regs. Publish: one
// DSMEM (value,seq) u64 per thread to rank kq. Poll: 1 u64/thread, tight spin.
// hT slices padded to 68 floats (16B-aligned) -> FMA h reads via LDS.128.
__global__ __launch_bounds__(256, 1) __cluster_dims__(4, 1, 1)
void scan_kernel(const float* __restrict__ hidden, const float* __restrict__ w_hh,
                 const float* __restrict__ b_hh, float* __restrict__ out) {
  __shared__ __align__(16) unsigned long long bufs[2][HH];  // [parity][col]
  __shared__ __align__(16) float hT[4 * 68];                // padded 64-col slices

  const int tid  = threadIdx.x;
  const int rank = blockIdx.x & 3;
  const int b    = blockIdx.x >> 2;    // batch (0..31)
  const int warp = tid >> 5;
  const int lane = tid & 31;
  const int kq   = lane & 3;           // K-slice [kq*64, kq*64+64) floats
  const int colL = warp * 8 + (lane >> 2);   // 0..63
  const int col  = rank * 64 + colL;   // global column (this CTA's output col)

  // ---- persistent weights: 3 gates x 32 k-pairs = 96 u64 regs ----
  uint64_t w2[3][32];
#pragma unroll
  for (int g = 0; g < 3; ++g) {
    const uint64_t* wp =
        (const uint64_t*)(w_hh + (size_t)(g * HH + col) * HH + kq * 64);
#pragma unroll
    for (int kp = 0; kp < 32; ++kp) w2[g][kp] = wp[kp];
  }
  const float br = b_hh[0 * HH + col];
  const float bz = b_hh[1 * HH + col];
  const float bn = b_hh[2 * HH + col];

  // ---- init ----
  for (int i = tid; i < 2 * HH; i += 256) ((unsigned long long*)bufs)[i] = 0ull;
  for (int i = tid; i < HH; i += 256)
    hT[(i >> 6) * 68 + (i & 63)] = hidden[(size_t)b * HH + i];
  float hold = hidden[(size_t)b * HH + col];   // register-carried h for own col
  __syncthreads();
  CLUSTER_SYNC_();   // zeroed bufs visible before any peer publishes

  const uint32_t pollBase = smem_u32(&bufs[0][0]) + (uint32_t)tid * 8u;
  const uint32_t dstA = smem_u32(&bufs[0][col]);       // parity-0 publish target
  const uint32_t dstB = dstA + (uint32_t)(HH * 8);     // parity-1 publish target
  const int hTpos = (tid >> 6) * 68 + (tid & 63);      // compact position (col=tid)

  // gi registers for current t (shared by both layer cells of t)
  const float* gp0 = g_gi + (size_t)b * 768 + col;
  float gir = __ldg(gp0);
  float giz = __ldg(gp0 + 256);
  float gin = __ldg(gp0 + 512);

  for (int cell = 0; cell < NCELL; ++cell) {
    // ---- poll own SMEM (1 u64/thread, tight spin), compact into padded hT ----
    if (cell > 0) {
      const uint32_t pa = pollBase + (uint32_t)((cell & 1) ? HH * 8 : 0);
      const uint32_t tgt = (uint32_t)cell;
      uint64_t v = ld_vol_u64(pa);
      int spins = 0;
      while ((uint32_t)(v >> 32) != tgt) {
        if (++spins > 512) __nanosleep(20);
        v = ld_vol_u64(pa);
      }
      hT[hTpos] = __uint_as_float((uint32_t)v);
      __syncthreads();
    }

    // ---- FMA: 96 fma2 over 16 LDS.128 h reads (3 gates x 32 k-pairs) ----
    uint64_t aR = pack2(0.f, 0.f), aZ = aR, aN = aR;
    const ulonglong2* H4 = (const ulonglong2*)(&hT[kq * 68]);
#pragma unroll
    for (int q = 0; q < 16; ++q) {
      const ulonglong2 hh = H4[q];
      fma2(aR, w2[0][2 * q], hh.x);
      fma2(aZ, w2[1][2 * q], hh.x);
      fma2(aN, w2[2][2 * q], hh.x);
      fma2(aR, w2[0][2 * q + 1], hh.y);
      fma2(aZ, w2[1][2 * q + 1], hh.y);
      fma2(aN, w2[2][2 * q + 1], hh.y);
    }
    float sR = hadd(aR), sZ = hadd(aZ), sN = hadd(aN);
    // butterfly over kq (lane bits 0..1): 2 rounds x 3 values
#pragma unroll
    for (int m = 1; m <= 2; m <<= 1) {
      sR += __shfl_xor_sync(0xffffffffu, sR, m);
      sZ += __shfl_xor_sync(0xffffffffu, sZ, m);
      sN += __shfl_xor_sync(0xffffffffu, sN, m);
    }

    // ---- gates (EX2 + fma-Newton reciprocal), redundant across kq lanes ----
    const float r = sig_f(gir + sR + br);
    const float z = sig_f(giz + sZ + bz);
    const float n = tanh_f(gin + r * (sN + bn));
    const float hn = (1.f - z) * n + z * hold;
    hold = hn;                                  // register-carried for next cell

    // ---- publish FIRST (critical path): each thread -> rank kq, 1 u64 ----
    if (cell + 1 < NCELL) {
      const uint64_t pkd =
          ((uint64_t)(uint32_t)(cell + 1) << 32) | (uint64_t)__float_as_uint(hn);
      st_cluster_u64(((cell + 1) & 1) ? dstB : dstA, (uint32_t)kq, pkd);
    }
    // ---- off critical path: output store + gi prefetch for next t ----
    if (cell & 1) {
      if (kq == 3)
        out[((size_t)(cell >> 1) * BB + b) * HH + col] = hn;
      if (cell + 1 < NCELL) {   // next cell starts a new t: reload gi (hidden)
        const float* gp =
            g_gi + ((size_t)((cell + 1) >> 1) * BB + b) * 768 + col;
        gir = __ldg(gp);
        giz = __ldg(gp + 256);
        gin = __ldg(gp + 512);
      }
    }
  }
  CLUSTER_SYNC_();   // no CTA exits while peers may still store into its SMEM
}

// ---------------- launch ----------------------------------------------------------
extern "C" void kernel_launch(void* const* d_in, const int* in_sizes, int n_in,
                              void* d_out, int out_size) {
  const float *input = 0, *hidden = 0, *w_ih = 0, *w_hh = 0, *b_ih = 0, *b_hh = 0;
  for (int i = 0; i < n_in; ++i) {
    long s = in_sizes[i];
    if (s == (long)BB * TT * HH) {
      input = (const float*)d_in[i];
    } else if (s == BB * HH && !hidden) {
      hidden = (const float*)d_in[i];
    } else if (s == 3 * HH * HH) {
      if (!w_ih) w_ih = (const float*)d_in[i]; else w_hh = (const float*)d_in[i];
    } else if (s == 3 * HH) {
      if (!b_ih) b_ih = (const float*)d_in[i]; else b_hh = (const float*)d_in[i];
    }
  }
  gi_kernel<<<dim3(TT, 6), 256>>>(input, w_ih, b_ih);
  scan_kernel<<<NCTA, 256>>>(hidden, w_hh, b_hh, (float*)d_out);
}

// round 17
// speedup vs baseline: 1.1102x; 1.0006x over previous
#include <cuda_runtime.h>
#include <cstdint>
#include <cstddef>

#define TT 2048
#define BB 32
#define HH 256
#define NCELL (TT * 2)
#define NCTA 128          // 32 clusters x 4 CTAs, one batch per cluster

// ---------------- global scratch (allocation-free) ------------------------------
__device__ float g_gi[(size_t)TT * BB * 3 * HH];   // x @ w_ih^T + b_ih  [T][B][768]

// ---------------- helpers ---------------------------------------------------------
__device__ __forceinline__ uint32_t smem_u32(const void* p) {
  uint32_t a;
  asm("{ .reg .u64 t; cvta.to.shared.u64 t, %1; cvt.u32.u64 %0, t; }"
      : "=r"(a) : "l"(p));
  return a;
}
__device__ __forceinline__ uint64_t pack2(float a, float b) {
  uint64_t r;
  asm("mov.b64 %0, {%1, %2};" : "=l"(r) : "f"(a), "f"(b));
  return r;
}
__device__ __forceinline__ void unpack2(float& a, float& b, uint64_t v) {
  asm("mov.b64 {%0, %1}, %2;" : "=f"(a), "=f"(b) : "l"(v));
}
__device__ __forceinline__ void fma2(uint64_t& d, uint64_t a, uint64_t b) {
  asm("fma.rn.f32x2 %0, %1, %2, %0;" : "+l"(d) : "l"(a), "l"(b));
}
__device__ __forceinline__ float hadd(uint64_t v) {
  float a, b;
  unpack2(a, b, v);
  return a + b;
}
// reciprocal: rcp.approx + FMA-form Newton step -> ~0.5-1 ulp (accurate class)
__device__ __forceinline__ float rcp_fma(float d) {
  float r;
  asm("rcp.approx.f32 %0, %1;" : "=f"(r) : "f"(d));
  const float e = __fmaf_rn(-d, r, 1.f);
  return __fmaf_rn(r, e, r);
}
__device__ __forceinline__ float sig_f(float x) {
  return rcp_fma(1.f + __expf(-x));
}
__device__ __forceinline__ float tanh_f(float x) {
  return __fmaf_rn(2.f, rcp_fma(1.f + __expf(-2.f * x)), -1.f);
}
// store (value,seq) u64 into CTA `rank`'s SMEM at this CTA's local offset
__device__ __forceinline__ void st_cluster_u64(uint32_t local_addr, uint32_t rank,
                                               uint64_t v) {
  asm volatile(
      "{\n\t.reg .b32 ra;\n\t"
      "mapa.shared::cluster.u32 ra, %0, %1;\n\t"
      "st.relaxed.cluster.shared::cluster.u64 [ra], %2;\n\t}"
      :: "r"(local_addr), "r"(rank), "l"(v) : "memory");
}
__device__ __forceinline__ uint64_t ld_vol_u64(uint32_t addr) {
  uint64_t v;
  asm volatile("ld.volatile.shared.u64 %0, [%1];" : "=l"(v) : "r"(addr) : "memory");
  return v;
}
#define CLUSTER_SYNC_()                                              \
  do {                                                               \
    asm volatile("barrier.cluster.arrive.aligned;" ::: "memory");    \
    asm volatile("barrier.cluster.wait.aligned;" ::: "memory");      \
  } while (0)

// ---------------- gi precompute (f32x2 packed over k-pairs) -----------------------
__global__ __launch_bounds__(256) void gi_kernel(
    const float* __restrict__ x, const float* __restrict__ w_ih,
    const float* __restrict__ b_ih) {
  __shared__ float xs[32 * 260];
  __shared__ float ws[128 * 18];
  const int t   = blockIdx.x;
  const int gc0 = blockIdx.y * 128;
  const int tid = threadIdx.x;

  for (int i = tid; i < 2048; i += 256) {
    int b = i >> 6;
    int c4 = (i & 63) << 2;
    float4 v = *(const float4*)(x + ((size_t)b * TT + t) * HH + c4);
    *(float4*)(xs + b * 260 + c4) = v;
  }

  const int bq = tid >> 5;
  const int gq = tid & 31;

  uint64_t acc2[4][4];
#pragma unroll
  for (int i = 0; i < 4; i++)
#pragma unroll
    for (int j = 0; j < 4; j++) acc2[i][j] = pack2(0.f, 0.f);

  for (int kt = 0; kt < 16; ++kt) {
    const int k0 = kt * 16;
    __syncthreads();
    for (int i = tid; i < 1024; i += 256) {
      int r = i >> 3;
      int c2 = (i & 7) << 1;
      *(float2*)(ws + r * 18 + c2) =
          *(const float2*)(w_ih + (size_t)(gc0 + r) * HH + k0 + c2);
    }
    __syncthreads();
#pragma unroll
    for (int kp = 0; kp < 8; ++kp) {
      const int kk = kp << 1;
      uint64_t w2[4];
#pragma unroll
      for (int j = 0; j < 4; j++)
        w2[j] = *(const uint64_t*)(ws + (gq + 32 * j) * 18 + kk);
#pragma unroll
      for (int i = 0; i < 4; i++) {
        const uint64_t x2 = *(const uint64_t*)(xs + (bq * 4 + i) * 260 + k0 + kk);
#pragma unroll
        for (int j = 0; j < 4; j++) fma2(acc2[i][j], x2, w2[j]);
      }
    }
  }
#pragma unroll
  for (int j = 0; j < 4; j++) {
    int g = gc0 + gq + 32 * j;
    float bias = b_ih[g];
#pragma unroll
    for (int i = 0; i < 4; i++) {
      float a, b;
      unpack2(a, b, acc2[i][j]);
      g_gi[((size_t)t * BB + (bq * 4 + i)) * 768 + g] = a + b + bias;
    }
  }
}

// ---------------- clustered recurrent scan: 4 CTAs / 1 batch ----------------------
// Thread = (col, kq): 64 cols x 4 K-slices. Weights in 96 u64 regs. Publish: one
// DSMEM (value,seq) u64 per thread to rank kq. Poll: 1 u64/thread, tight spin.
// hT slices padded to 68 floats (16B-aligned) -> FMA h reads via LDS.128.
__global__ __launch_bounds__(256, 1) __cluster_dims__(4, 1, 1)
void scan_kernel(const float* __restrict__ hidden, const float* __restrict__ w_hh,
                 const float* __restrict__ b_hh, float* __restrict__ out) {
  __shared__ __align__(16) unsigned long long bufs[2][HH];  // [parity][col]
  __shared__ __align__(16) float hT[4 * 68];                // padded 64-col slices

  const int tid  = threadIdx.x;
  const int rank = blockIdx.x & 3;
  const int b    = blockIdx.x >> 2;    // batch (0..31)
  const int warp = tid >> 5;
  const int lane = tid & 31;
  const int kq   = lane & 3;           // K-slice [kq*64, kq*64+64) floats
  const int colL = warp * 8 + (lane >> 2);   // 0..63
  const int col  = rank * 64 + colL;   // global column (this CTA's output col)

  // ---- persistent weights: 3 gates x 32 k-pairs = 96 u64 regs ----
  uint64_t w2[3][32];
#pragma unroll
  for (int g = 0; g < 3; ++g) {
    const uint64_t* wp =
        (const uint64_t*)(w_hh + (size_t)(g * HH + col) * HH + kq * 64);
#pragma unroll
    for (int kp = 0; kp < 32; ++kp) w2[g][kp] = wp[kp];
  }
  const float br = b_hh[0 * HH + col];
  const float bz = b_hh[1 * HH + col];
  const float bn = b_hh[2 * HH + col];

  // ---- init ----
  for (int i = tid; i < 2 * HH; i += 256) ((unsigned long long*)bufs)[i] = 0ull;
  for (int i = tid; i < HH; i += 256)
    hT[(i >> 6) * 68 + (i & 63)] = hidden[(size_t)b * HH + i];
  float hold = hidden[(size_t)b * HH + col];   // register-carried h for own col
  __syncthreads();
  CLUSTER_SYNC_();   // zeroed bufs visible before any peer publishes

  const uint32_t pollBase = smem_u32(&bufs[0][0]) + (uint32_t)tid * 8u;
  const uint32_t dstA = smem_u32(&bufs[0][col]);       // parity-0 publish target
  const uint32_t dstB = dstA + (uint32_t)(HH * 8);     // parity-1 publish target
  const int hTpos = (tid >> 6) * 68 + (tid & 63);      // compact position (col=tid)

  // gi registers for current t (shared by both layer cells of t)
  const float* gp0 = g_gi + (size_t)b * 768 + col;
  float gir = __ldg(gp0);
  float giz = __ldg(gp0 + 256);
  float gin = __ldg(gp0 + 512);

  for (int cell = 0; cell < NCELL; ++cell) {
    // ---- poll own SMEM (1 u64/thread, tight spin), compact into padded hT ----
    if (cell > 0) {
      const uint32_t pa = pollBase + (uint32_t)((cell & 1) ? HH * 8 : 0);
      const uint32_t tgt = (uint32_t)cell;
      uint64_t v = ld_vol_u64(pa);
      int spins = 0;
      while ((uint32_t)(v >> 32) != tgt) {
        if (++spins > 512) __nanosleep(20);
        v = ld_vol_u64(pa);
      }
      hT[hTpos] = __uint_as_float((uint32_t)v);
      __syncthreads();
    }

    // ---- FMA: 96 fma2 over 16 LDS.128 h reads (3 gates x 32 k-pairs) ----
    uint64_t aR = pack2(0.f, 0.f), aZ = aR, aN = aR;
    const ulonglong2* H4 = (const ulonglong2*)(&hT[kq * 68]);
#pragma unroll
    for (int q = 0; q < 16; ++q) {
      const ulonglong2 hh = H4[q];
      fma2(aR, w2[0][2 * q], hh.x);
      fma2(aZ, w2[1][2 * q], hh.x);
      fma2(aN, w2[2][2 * q], hh.x);
      fma2(aR, w2[0][2 * q + 1], hh.y);
      fma2(aZ, w2[1][2 * q + 1], hh.y);
      fma2(aN, w2[2][2 * q + 1], hh.y);
    }
    float sR = hadd(aR), sZ = hadd(aZ), sN = hadd(aN);
    // butterfly over kq (lane bits 0..1): 2 rounds x 3 values
#pragma unroll
    for (int m = 1; m <= 2; m <<= 1) {
      sR += __shfl_xor_sync(0xffffffffu, sR, m);
      sZ += __shfl_xor_sync(0xffffffffu, sZ, m);
      sN += __shfl_xor_sync(0xffffffffu, sN, m);
    }

    // ---- gates (EX2 + fma-Newton reciprocal), redundant across kq lanes ----
    const float r = sig_f(gir + sR + br);
    const float z = sig_f(giz + sZ + bz);
    const float n = tanh_f(gin + r * (sN + bn));
    const float hn = (1.f - z) * n + z * hold;
    hold = hn;                                  // register-carried for next cell

    // ---- publish FIRST (critical path): each thread -> rank kq, 1 u64 ----
    if (cell + 1 < NCELL) {
      const uint64_t pkd =
          ((uint64_t)(uint32_t)(cell + 1) << 32) | (uint64_t)__float_as_uint(hn);
      st_cluster_u64(((cell + 1) & 1) ? dstB : dstA, (uint32_t)kq, pkd);
    }
    // ---- off critical path: output store + gi prefetch for next t ----
    if (cell & 1) {
      if (kq == 3)
        out[((size_t)(cell >> 1) * BB + b) * HH + col] = hn;
      if (cell + 1 < NCELL) {   // next cell starts a new t: reload gi (hidden)
        const float* gp =
            g_gi + ((size_t)((cell + 1) >> 1) * BB + b) * 768 + col;
        gir = __ldg(gp);
        giz = __ldg(gp + 256);
        gin = __ldg(gp + 512);
      }
    }
  }
  CLUSTER_SYNC_();   // no CTA exits while peers may still store into its SMEM
}

// ---------------- launch ----------------------------------------------------------
extern "C" void kernel_launch(void* const* d_in, const int* in_sizes, int n_in,
                              void* d_out, int out_size) {
  const float *input = 0, *hidden = 0, *w_ih = 0, *w_hh = 0, *b_ih = 0, *b_hh = 0;
  for (int i = 0; i < n_in; ++i) {
    long s = in_sizes[i];
    if (s == (long)BB * TT * HH) {
      input = (const float*)d_in[i];
    } else if (s == BB * HH && !hidden) {
      hidden = (const float*)d_in[i];
    } else if (s == 3 * HH * HH) {
      if (!w_ih) w_ih = (const float*)d_in[i]; else w_hh = (const float*)d_in[i];
    } else if (s == 3 * HH) {
      if (!b_ih) b_ih = (const float*)d_in[i]; else b_hh = (const float*)d_in[i];
    }
  }
  gi_kernel<<<dim3(TT, 6), 256>>>(input, w_ih, b_ih);
  scan_kernel<<<NCTA, 256>>>(hidden, w_hh, b_hh, (float*)d_out);
}